// round 10
// baseline (speedup 1.0000x reference)
#include <cuda_runtime.h>
#include <math.h>

#define N_NODES 4096
#define FIN     256
#define NHEAD   4
#define FHID    64
#define FFIN    64
#define NPROJ   16
#define MAXD    128

// ---------------- scratch ----------------
__device__ int   g_cols[2][N_NODES][MAXD];
__device__ int   g_deg [2][N_NODES];
__device__ float g_Wh  [N_NODES][512];      // x @ Wcat   (cols: g*256 + h*64 + f)
__device__ float g_s1t [2][N_NODES][4];     // layer-1 src logits, 4 heads packed
__device__ float g_s2t [2][N_NODES][4];     // layer-1 dst logits, 4 heads packed
__device__ float g_hcat[2][N_NODES][256];   // layer-1 outputs (head-concat)
__device__ float g_Wh2 [2][N_NODES][64];
__device__ float g_s1o [2][N_NODES];
__device__ float g_s2o [2][N_NODES];

__device__ __forceinline__ float lkexp(float z) {
    z = z >= 0.f ? z : 0.2f * z;
    return __expf(z);
}
__device__ __forceinline__ float elu1(float v) {
    return v > 0.f ? v : (__expf(v) - 1.f);
}

// =====================================================================
// CSR build (standalone, low regs, MLP=4): one warp per (graph,row).
// =====================================================================
__device__ __forceinline__ void place_bits(unsigned nb, int cb, int& pos, int* __restrict__ row) {
    while (nb) {
        int b = __ffs(nb) - 1;
        nb &= nb - 1;
        if (pos < MAXD) row[pos] = cb + b;
        pos++;
    }
}

__global__ void csr_build(const float* __restrict__ m0, const float* __restrict__ m1) {
    int tid  = threadIdx.x;
    int w    = blockIdx.x * 8 + (tid >> 5);
    int lane = tid & 31;
    int g = w >> 12, r = w & 4095;
    const float4* mask = (const float4*)((g ? m1 : m0) + (size_t)r * N_NODES);
    int* row = &g_cols[g][r][0];
    int cnt = 0;
    for (int jb = 0; jb < 1024; jb += 128) {
        float4 v0 = mask[jb + lane];
        float4 v1 = mask[jb + 32 + lane];
        float4 v2 = mask[jb + 64 + lane];
        float4 v3 = mask[jb + 96 + lane];
        unsigned n0 = (v0.x > 0.f) | ((v0.y > 0.f) << 1) | ((v0.z > 0.f) << 2) | ((v0.w > 0.f) << 3);
        unsigned n1 = (v1.x > 0.f) | ((v1.y > 0.f) << 1) | ((v1.z > 0.f) << 2) | ((v1.w > 0.f) << 3);
        unsigned n2 = (v2.x > 0.f) | ((v2.y > 0.f) << 1) | ((v2.z > 0.f) << 2) | ((v2.w > 0.f) << 3);
        unsigned n3 = (v3.x > 0.f) | ((v3.y > 0.f) << 1) | ((v3.z > 0.f) << 2) | ((v3.w > 0.f) << 3);
        int c = __popc(n0) + __popc(n1) + __popc(n2) + __popc(n3);
        int s = c;
        #pragma unroll
        for (int off = 1; off < 32; off <<= 1) {
            int t = __shfl_up_sync(0xffffffffu, s, off);
            if (lane >= off) s += t;
        }
        int pos = cnt + s - c;
        cnt += __shfl_sync(0xffffffffu, s, 31);
        if (c) {
            place_bits(n0, (jb + lane) * 4,      pos, row);
            place_bits(n1, (jb + 32 + lane) * 4, pos, row);
            place_bits(n2, (jb + 64 + lane) * 4, pos, row);
            place_bits(n3, (jb + 96 + lane) * 4, pos, row);
        }
    }
    if (lane == 0) g_deg[g][r] = cnt < MAXD ? cnt : MAXD;
}

// =====================================================================
// GEMM1: Wh = x @ Wcat, tile 128x128, 8x8 microtile, double-buffered.
// grid (32, 4), 256 threads. Tile cols span 2 heads. + s1/s2 epilogue.
// =====================================================================
__global__ void __launch_bounds__(256) gemm1(
        const float* __restrict__ x,
        const float* __restrict__ W1, const float* __restrict__ W2,
        const float* __restrict__ a1, const float* __restrict__ a2) {
    __shared__ float As[2][16][132];
    __shared__ float Bs[2][16][128];
    int tid = threadIdx.x;
    int m0r = blockIdx.x * 128;
    int by  = blockIdx.y;                   // 0..3, covers heads (2by, 2by+1)
    int gsel = by >> 1;
    int h0   = (by * 2) & 3;                // first head in tile
    const float* W  = gsel ? W2 : W1;       // [4,256,64]
    const float* aa = gsel ? a2 : a1;       // [4,128]
    int tx = tid & 15, ty = tid >> 4;

    // loaders: A 128x16 = 512 f4 (2/thread), B 16x128 = 512 f4 (2/thread)
    int a_m0 = tid >> 2,        a_k4 = tid & 3;          // elem tid
    int a_m1 = (256 + tid) >> 2, a_k41 = (256 + tid) & 3; // elem 256+tid
    int b_k0 = tid >> 5,        b_c0 = (tid & 31) * 4;
    int b_k1 = (256 + tid) >> 5, b_c1 = ((256 + tid) & 31) * 4;
    const float* Ap0 = x + (size_t)(m0r + a_m0) * FIN;
    const float* Ap1 = x + (size_t)(m0r + a_m1) * FIN;
    // B gmem addr for (k, c): W[((h0 + (c>>6))*256 + k)*64 + (c&63)]
    const float* Bp0 = W + ((size_t)(h0 + (b_c0 >> 6)) * FIN) * FHID + (b_c0 & 63);
    const float* Bp1 = W + ((size_t)(h0 + (b_c1 >> 6)) * FIN) * FHID + (b_c1 & 63);

    float4 fa0 = *(const float4*)(Ap0 + a_k4 * 4);
    float4 fa1 = *(const float4*)(Ap1 + a_k41 * 4);
    float4 fb0 = *(const float4*)(Bp0 + (size_t)b_k0 * FHID);
    float4 fb1 = *(const float4*)(Bp1 + (size_t)b_k1 * FHID);
    As[0][a_k4 * 4 + 0][a_m0] = fa0.x; As[0][a_k4 * 4 + 1][a_m0] = fa0.y;
    As[0][a_k4 * 4 + 2][a_m0] = fa0.z; As[0][a_k4 * 4 + 3][a_m0] = fa0.w;
    As[0][a_k41 * 4 + 0][a_m1] = fa1.x; As[0][a_k41 * 4 + 1][a_m1] = fa1.y;
    As[0][a_k41 * 4 + 2][a_m1] = fa1.z; As[0][a_k41 * 4 + 3][a_m1] = fa1.w;
    *(float4*)&Bs[0][b_k0][b_c0] = fb0;
    *(float4*)&Bs[0][b_k1][b_c1] = fb1;
    __syncthreads();

    float acc[8][8] = {};
    #pragma unroll
    for (int t = 0; t < 16; t++) {
        int cur = t & 1;
        if (t < 15) {
            int kb = (t + 1) * 16;
            fa0 = *(const float4*)(Ap0 + kb + a_k4 * 4);
            fa1 = *(const float4*)(Ap1 + kb + a_k41 * 4);
            fb0 = *(const float4*)(Bp0 + (size_t)(kb + b_k0) * FHID);
            fb1 = *(const float4*)(Bp1 + (size_t)(kb + b_k1) * FHID);
        }
        #pragma unroll
        for (int kk = 0; kk < 16; kk++) {
            float4 av0 = *(const float4*)&As[cur][kk][ty * 8];
            float4 av1 = *(const float4*)&As[cur][kk][ty * 8 + 4];
            float4 bv0 = *(const float4*)&Bs[cur][kk][tx * 4];
            float4 bv1 = *(const float4*)&Bs[cur][kk][64 + tx * 4];
            float a[8] = {av0.x, av0.y, av0.z, av0.w, av1.x, av1.y, av1.z, av1.w};
            float b[8] = {bv0.x, bv0.y, bv0.z, bv0.w, bv1.x, bv1.y, bv1.z, bv1.w};
            #pragma unroll
            for (int r = 0; r < 8; r++)
                #pragma unroll
                for (int c = 0; c < 8; c++)
                    acc[r][c] += a[r] * b[c];
        }
        if (t < 15) {
            int nxt = cur ^ 1;
            As[nxt][a_k4 * 4 + 0][a_m0] = fa0.x; As[nxt][a_k4 * 4 + 1][a_m0] = fa0.y;
            As[nxt][a_k4 * 4 + 2][a_m0] = fa0.z; As[nxt][a_k4 * 4 + 3][a_m0] = fa0.w;
            As[nxt][a_k41 * 4 + 0][a_m1] = fa1.x; As[nxt][a_k41 * 4 + 1][a_m1] = fa1.y;
            As[nxt][a_k41 * 4 + 2][a_m1] = fa1.z; As[nxt][a_k41 * 4 + 3][a_m1] = fa1.w;
            *(float4*)&Bs[nxt][b_k0][b_c0] = fb0;
            *(float4*)&Bs[nxt][b_k1][b_c1] = fb1;
        }
        __syncthreads();
    }

    int n0 = by * 128;
    #pragma unroll
    for (int r = 0; r < 8; r++) {
        int m = m0r + ty * 8 + r;
        float4 v0 = make_float4(acc[r][0], acc[r][1], acc[r][2], acc[r][3]);
        float4 v1 = make_float4(acc[r][4], acc[r][5], acc[r][6], acc[r][7]);
        *(float4*)&g_Wh[m][n0 + tx * 4]      = v0;
        *(float4*)&g_Wh[m][n0 + 64 + tx * 4] = v1;
    }
    // s1/s2 epilogue for both heads in this tile
    #pragma unroll
    for (int gr = 0; gr < 2; gr++) {
        int h = h0 + gr;
        const float* av = aa + h * 128;
        float a_s[4], a_d[4];
        #pragma unroll
        for (int c = 0; c < 4; c++) {
            a_s[c] = __ldg(av + tx * 4 + c);
            a_d[c] = __ldg(av + 64 + tx * 4 + c);
        }
        #pragma unroll
        for (int r = 0; r < 8; r++) {
            float s1 = 0.f, s2 = 0.f;
            #pragma unroll
            for (int c = 0; c < 4; c++) {
                float acv = acc[r][gr * 4 + c];
                s1 += acv * a_s[c];
                s2 += acv * a_d[c];
            }
            #pragma unroll
            for (int off = 1; off < 16; off <<= 1) {
                s1 += __shfl_xor_sync(0xffffffffu, s1, off);
                s2 += __shfl_xor_sync(0xffffffffu, s2, off);
            }
            if (tx == 0) {
                int m = m0r + ty * 8 + r;
                g_s1t[gsel][m][h] = s1;
                g_s2t[gsel][m][h] = s2;
            }
        }
    }
}

// ---- 4-head gather chunk (attn1) ----
__device__ __forceinline__ void gat_chunk1(const float* __restrict__ tab, int lim,
                                           int cj, float4 ej,
                                           float& ax0, float& ay0, float& ax1, float& ay1,
                                           float& ax2, float& ay2, float& ax3, float& ay3) {
    int kk = 0;
    for (; kk + 2 <= lim; kk += 2) {
        int   ca  = __shfl_sync(0xffffffffu, cj, kk);
        int   cb  = __shfl_sync(0xffffffffu, cj, kk + 1);
        float ea0 = __shfl_sync(0xffffffffu, ej.x, kk);
        float ea1 = __shfl_sync(0xffffffffu, ej.y, kk);
        float ea2 = __shfl_sync(0xffffffffu, ej.z, kk);
        float ea3 = __shfl_sync(0xffffffffu, ej.w, kk);
        float eb0 = __shfl_sync(0xffffffffu, ej.x, kk + 1);
        float eb1 = __shfl_sync(0xffffffffu, ej.y, kk + 1);
        float eb2 = __shfl_sync(0xffffffffu, ej.z, kk + 1);
        float eb3 = __shfl_sync(0xffffffffu, ej.w, kk + 1);
        const float* ra = tab + (size_t)ca * 512;
        const float* rb = tab + (size_t)cb * 512;
        float2 va0 = *(const float2*)(ra);
        float2 va1 = *(const float2*)(ra + 64);
        float2 va2 = *(const float2*)(ra + 128);
        float2 va3 = *(const float2*)(ra + 192);
        float2 vb0 = *(const float2*)(rb);
        float2 vb1 = *(const float2*)(rb + 64);
        float2 vb2 = *(const float2*)(rb + 128);
        float2 vb3 = *(const float2*)(rb + 192);
        ax0 += ea0 * va0.x + eb0 * vb0.x;  ay0 += ea0 * va0.y + eb0 * vb0.y;
        ax1 += ea1 * va1.x + eb1 * vb1.x;  ay1 += ea1 * va1.y + eb1 * vb1.y;
        ax2 += ea2 * va2.x + eb2 * vb2.x;  ay2 += ea2 * va2.y + eb2 * vb2.y;
        ax3 += ea3 * va3.x + eb3 * vb3.x;  ay3 += ea3 * va3.y + eb3 * vb3.y;
    }
    if (kk < lim) {
        int   ca  = __shfl_sync(0xffffffffu, cj, kk);
        float ea0 = __shfl_sync(0xffffffffu, ej.x, kk);
        float ea1 = __shfl_sync(0xffffffffu, ej.y, kk);
        float ea2 = __shfl_sync(0xffffffffu, ej.z, kk);
        float ea3 = __shfl_sync(0xffffffffu, ej.w, kk);
        const float* ra = tab + (size_t)ca * 512;
        float2 va0 = *(const float2*)(ra);
        float2 va1 = *(const float2*)(ra + 64);
        float2 va2 = *(const float2*)(ra + 128);
        float2 va3 = *(const float2*)(ra + 192);
        ax0 += ea0 * va0.x;  ay0 += ea0 * va0.y;
        ax1 += ea1 * va1.x;  ay1 += ea1 * va1.y;
        ax2 += ea2 * va2.x;  ay2 += ea2 * va2.y;
        ax3 += ea3 * va3.x;  ay3 += ea3 * va3.y;
    }
}

// =====================================================================
// Layer-1 attention: ONE warp per (node, graph), all 4 heads together.
// =====================================================================
__global__ void attn_layer1() {
    int tid  = threadIdx.x;
    int lane = tid & 31;
    int w    = tid >> 5;
    int n    = w >> 1;
    int g    = w & 1;
    int i    = blockIdx.x * 4 + n;

    int d = g_deg[g][i];
    float4 s1 = *(const float4*)&g_s1t[g][i][0];

    int c0 = 0, c1 = 0;
    float4 e0 = make_float4(0.f, 0.f, 0.f, 0.f);
    float4 e1 = make_float4(0.f, 0.f, 0.f, 0.f);
    if (lane < d) {
        c0 = g_cols[g][i][lane];
        float4 s2 = *(const float4*)&g_s2t[g][c0][0];
        e0.x = lkexp(s1.x + s2.x);  e0.y = lkexp(s1.y + s2.y);
        e0.z = lkexp(s1.z + s2.z);  e0.w = lkexp(s1.w + s2.w);
    }
    if (lane + 32 < d) {
        c1 = g_cols[g][i][lane + 32];
        float4 s2 = *(const float4*)&g_s2t[g][c1][0];
        e1.x = lkexp(s1.x + s2.x);  e1.y = lkexp(s1.y + s2.y);
        e1.z = lkexp(s1.z + s2.z);  e1.w = lkexp(s1.w + s2.w);
    }
    float sx = e0.x + e1.x, sy = e0.y + e1.y, sz = e0.z + e1.z, sw = e0.w + e1.w;
    #pragma unroll
    for (int off = 16; off; off >>= 1) {
        sx += __shfl_xor_sync(0xffffffffu, sx, off);
        sy += __shfl_xor_sync(0xffffffffu, sy, off);
        sz += __shfl_xor_sync(0xffffffffu, sz, off);
        sw += __shfl_xor_sync(0xffffffffu, sw, off);
    }
    float ix = 1.f / sx, iy = 1.f / sy, iz = 1.f / sz, iw = 1.f / sw;

    const float* tab = &g_Wh[0][g * 256 + 2 * lane];
    float ax0 = 0.f, ay0 = 0.f, ax1 = 0.f, ay1 = 0.f;
    float ax2 = 0.f, ay2 = 0.f, ax3 = 0.f, ay3 = 0.f;
    int lim0 = d < 32 ? d : 32;
    int lim1 = d - 32; lim1 = lim1 < 0 ? 0 : lim1;
    gat_chunk1(tab, lim0, c0, e0, ax0, ay0, ax1, ay1, ax2, ay2, ax3, ay3);
    gat_chunk1(tab, lim1, c1, e1, ax0, ay0, ax1, ay1, ax2, ay2, ax3, ay3);

    float* orow = &g_hcat[g][i][2 * lane];
    float2 o;
    o.x = elu1(ax0 * ix);  o.y = elu1(ay0 * ix);  *(float2*)(orow)       = o;
    o.x = elu1(ax1 * iy);  o.y = elu1(ay1 * iy);  *(float2*)(orow + 64)  = o;
    o.x = elu1(ax2 * iz);  o.y = elu1(ay2 * iz);  *(float2*)(orow + 128) = o;
    o.x = elu1(ax3 * iw);  o.y = elu1(ay3 * iw);  *(float2*)(orow + 192) = o;
}

// =====================================================================
// GEMM2: Wh2_g = hcat_g @ Wo_g, tile 32x64, 4x4 microtile, 128 threads,
// double-buffered, grid (128, 2). + s1o/s2o epilogue.
// =====================================================================
__global__ void gemm2f(const float* __restrict__ Wo1, const float* __restrict__ Wo2,
                       const float* __restrict__ ao1, const float* __restrict__ ao2) {
    __shared__ float As[2][16][36];
    __shared__ float Bs[2][16][64];
    int g = blockIdx.y;
    int m0r = blockIdx.x * 32;
    const float* A  = &g_hcat[g][0][0];
    const float* B  = g ? Wo2 : Wo1;
    const float* ao = g ? ao2 : ao1;
    int tid = threadIdx.x;               // 128 threads
    int tx = tid & 15, ty = tid >> 4;    // ty 0..7

    int am = tid >> 2, ak4 = tid & 3;                     // A: 128 f4, 1/thread
    int b_k0 = tid >> 4, b_c0 = (tid & 15) * 4;           // B: 256 f4, 2/thread
    int b_k1 = (128 + tid) >> 4, b_c1 = ((128 + tid) & 15) * 4;
    const float* Aptr = A + (size_t)(m0r + am) * 256;

    float4 fa  = *(const float4*)(Aptr + ak4 * 4);
    float4 fb0 = *(const float4*)(B + (size_t)b_k0 * 64 + b_c0);
    float4 fb1 = *(const float4*)(B + (size_t)b_k1 * 64 + b_c1);
    As[0][ak4 * 4 + 0][am] = fa.x; As[0][ak4 * 4 + 1][am] = fa.y;
    As[0][ak4 * 4 + 2][am] = fa.z; As[0][ak4 * 4 + 3][am] = fa.w;
    *(float4*)&Bs[0][b_k0][b_c0] = fb0;
    *(float4*)&Bs[0][b_k1][b_c1] = fb1;
    __syncthreads();

    float acc[4][4] = {};
    #pragma unroll
    for (int t = 0; t < 16; t++) {
        int cur = t & 1;
        if (t < 15) {
            int kb = (t + 1) * 16;
            fa  = *(const float4*)(Aptr + kb + ak4 * 4);
            fb0 = *(const float4*)(B + (size_t)(kb + b_k0) * 64 + b_c0);
            fb1 = *(const float4*)(B + (size_t)(kb + b_k1) * 64 + b_c1);
        }
        #pragma unroll
        for (int kk = 0; kk < 16; kk++) {
            float4 av = *(const float4*)&As[cur][kk][ty * 4];
            float4 bv = *(const float4*)&Bs[cur][kk][tx * 4];
            float a[4] = {av.x, av.y, av.z, av.w};
            float b[4] = {bv.x, bv.y, bv.z, bv.w};
            #pragma unroll
            for (int r = 0; r < 4; r++)
                #pragma unroll
                for (int c = 0; c < 4; c++)
                    acc[r][c] += a[r] * b[c];
        }
        if (t < 15) {
            int nxt = cur ^ 1;
            As[nxt][ak4 * 4 + 0][am] = fa.x; As[nxt][ak4 * 4 + 1][am] = fa.y;
            As[nxt][ak4 * 4 + 2][am] = fa.z; As[nxt][ak4 * 4 + 3][am] = fa.w;
            *(float4*)&Bs[nxt][b_k0][b_c0] = fb0;
            *(float4*)&Bs[nxt][b_k1][b_c1] = fb1;
        }
        __syncthreads();
    }

    #pragma unroll
    for (int r = 0; r < 4; r++) {
        int m = m0r + ty * 4 + r;
        float4 v = make_float4(acc[r][0], acc[r][1], acc[r][2], acc[r][3]);
        *(float4*)&g_Wh2[g][m][tx * 4] = v;
    }
    float a_s[4], a_d[4];
    #pragma unroll
    for (int c = 0; c < 4; c++) {
        a_s[c] = __ldg(ao + tx * 4 + c);
        a_d[c] = __ldg(ao + 64 + tx * 4 + c);
    }
    #pragma unroll
    for (int r = 0; r < 4; r++) {
        float s1 = 0.f, s2 = 0.f;
        #pragma unroll
        for (int c = 0; c < 4; c++) { s1 += acc[r][c] * a_s[c]; s2 += acc[r][c] * a_d[c]; }
        #pragma unroll
        for (int off = 1; off < 16; off <<= 1) {
            s1 += __shfl_xor_sync(0xffffffffu, s1, off);
            s2 += __shfl_xor_sync(0xffffffffu, s2, off);
        }
        if (tx == 0) {
            int m = m0r + ty * 4 + r;
            g_s1o[g][m] = s1;
            g_s2o[g][m] = s2;
        }
    }
}

// ---- scalar gather chunk (attn2), MLP=4, stride 64 floats ----
__device__ __forceinline__ void gat_chunk2(const float* __restrict__ tab, int lim,
                                           int cj, float ej, float& ax, float& ay) {
    int kk = 0;
    for (; kk + 4 <= lim; kk += 4) {
        int   c0 = __shfl_sync(0xffffffffu, cj, kk);
        int   c1 = __shfl_sync(0xffffffffu, cj, kk + 1);
        int   c2 = __shfl_sync(0xffffffffu, cj, kk + 2);
        int   c3 = __shfl_sync(0xffffffffu, cj, kk + 3);
        float e0 = __shfl_sync(0xffffffffu, ej, kk);
        float e1 = __shfl_sync(0xffffffffu, ej, kk + 1);
        float e2 = __shfl_sync(0xffffffffu, ej, kk + 2);
        float e3 = __shfl_sync(0xffffffffu, ej, kk + 3);
        float2 v0 = *(const float2*)(tab + (size_t)c0 * 64);
        float2 v1 = *(const float2*)(tab + (size_t)c1 * 64);
        float2 v2 = *(const float2*)(tab + (size_t)c2 * 64);
        float2 v3 = *(const float2*)(tab + (size_t)c3 * 64);
        ax += e0 * v0.x + e1 * v1.x + e2 * v2.x + e3 * v3.x;
        ay += e0 * v0.y + e1 * v1.y + e2 * v2.y + e3 * v3.y;
    }
    for (; kk < lim; kk++) {
        int   c = __shfl_sync(0xffffffffu, cj, kk);
        float e = __shfl_sync(0xffffffffu, ej, kk);
        float2 v = *(const float2*)(tab + (size_t)c * 64);
        ax += e * v.x;
        ay += e * v.y;
    }
}

// =====================================================================
// Layer-2 attention + ELU + semantic fusion.
// =====================================================================
__global__ void attn2_final(const float* __restrict__ Wp1, const float* __restrict__ bp1,
                            const float* __restrict__ Wp2, float* __restrict__ out) {
    int tid  = threadIdx.x;
    int lane = tid & 31;
    int w    = tid >> 5;        // 0..7
    int n    = w >> 1;          // node slot 0..3
    int g    = w & 1;
    int i    = blockIdx.x * 4 + n;

    __shared__ float se[4][2][64];
    __shared__ float sw[4][2];

    int d = g_deg[g][i];
    float s1v = g_s1o[g][i];
    int c0 = 0, c1 = 0;
    float e0 = 0.f, e1 = 0.f;
    if (lane < d) {
        c0 = g_cols[g][i][lane];
        e0 = lkexp(s1v + g_s2o[g][c0]);
    }
    if (lane + 32 < d) {
        c1 = g_cols[g][i][lane + 32];
        e1 = lkexp(s1v + g_s2o[g][c1]);
    }
    float sum = e0 + e1;
    #pragma unroll
    for (int off = 16; off; off >>= 1) sum += __shfl_xor_sync(0xffffffffu, sum, off);
    float inv = 1.f / sum;

    const float* tab = &g_Wh2[g][0][2 * lane];
    float ax = 0.f, ay = 0.f;
    int lim0 = d < 32 ? d : 32;
    int lim1 = d - 32; lim1 = lim1 < 0 ? 0 : lim1;
    gat_chunk2(tab, lim0, c0, e0, ax, ay);
    gat_chunk2(tab, lim1, c1, e1, ax, ay);

    ax *= inv; ay *= inv;
    se[n][g][2 * lane]     = elu1(ax);
    se[n][g][2 * lane + 1] = elu1(ay);
    __syncthreads();

    if (tid < 128) {
        int pn = tid >> 5, pg = (tid >> 4) & 1, p = tid & 15;
        float s = __ldg(bp1 + p);
        #pragma unroll
        for (int f = 0; f < 64; f++) s += se[pn][pg][f] * __ldg(Wp1 + f * NPROJ + p);
        float e2x = __expf(2.f * s);
        float t = __fdividef(e2x - 1.f, e2x + 1.f);
        float wv = t * __ldg(Wp2 + p);
        wv += __shfl_xor_sync(0xffffffffu, wv, 1);
        wv += __shfl_xor_sync(0xffffffffu, wv, 2);
        wv += __shfl_xor_sync(0xffffffffu, wv, 4);
        wv += __shfl_xor_sync(0xffffffffu, wv, 8);
        if (p == 0) sw[pn][pg] = wv;
    }
    __syncthreads();

    int on = tid >> 6, f = tid & 63;
    float w0 = sw[on][0], w1 = sw[on][1];
    float mm = fmaxf(w0, w1);
    float b0 = __expf(w0 - mm), b1 = __expf(w1 - mm);
    float ib = 1.f / (b0 + b1);
    int oi = blockIdx.x * 4 + on;
    out[(size_t)oi * 64 + f] = (b0 * se[on][0][f] + b1 * se[on][1][f]) * ib;
}

// ---------------- launch ----------------
extern "C" void kernel_launch(void* const* d_in, const int* in_sizes, int n_in,
                              void* d_out, int out_size) {
    const float* x    = (const float*)d_in[0];
    const float* sadj = (const float*)d_in[1];
    const float* sadj2= (const float*)d_in[2];
    const float* W1   = (const float*)d_in[3];
    const float* a1   = (const float*)d_in[4];
    const float* Wo1  = (const float*)d_in[5];
    const float* ao1  = (const float*)d_in[6];
    const float* W2   = (const float*)d_in[7];
    const float* a2   = (const float*)d_in[8];
    const float* Wo2  = (const float*)d_in[9];
    const float* ao2  = (const float*)d_in[10];
    const float* Wp1  = (const float*)d_in[11];
    const float* bp1  = (const float*)d_in[12];
    const float* Wp2  = (const float*)d_in[13];
    float* out = (float*)d_out;

    csr_build<<<1024, 256>>>(sadj, sadj2);
    gemm1<<<dim3(32, 4), 256>>>(x, W1, W2, a1, a2);
    attn_layer1<<<1024, 256>>>();
    gemm2f<<<dim3(128, 2), 128>>>(Wo1, Wo2, ao1, ao2);
    attn2_final<<<1024, 256>>>(Wp1, bp1, Wp2, out);
}

// round 11
// speedup vs baseline: 1.3734x; 1.3734x over previous
#include <cuda_runtime.h>
#include <math.h>

#define N_NODES 4096
#define FIN     256
#define NHEAD   4
#define FHID    64
#define FFIN    64
#define NPROJ   16
#define MAXD    128

// ---------------- scratch ----------------
__device__ int   g_cols[2][N_NODES][MAXD];
__device__ int   g_deg [2][N_NODES];
__device__ float g_Wh  [N_NODES][512];      // x @ Wcat   (cols: g*256 + h*64 + f)
__device__ float g_s1t [2][N_NODES][4];     // layer-1 src logits, 4 heads packed
__device__ float g_s2t [2][N_NODES][4];     // layer-1 dst logits, 4 heads packed
__device__ float g_hcat[2][N_NODES][256];   // layer-1 outputs (head-concat)
__device__ float g_Wh2 [2][N_NODES][64];
__device__ float g_s1o [2][N_NODES];
__device__ float g_s2o [2][N_NODES];

__device__ __forceinline__ float lkexp(float z) {
    z = z >= 0.f ? z : 0.2f * z;
    return __expf(z);
}
__device__ __forceinline__ float elu1(float v) {
    return v > 0.f ? v : (__expf(v) - 1.f);
}

// =====================================================================
// CSR build (standalone, low regs, MLP=4): one warp per (graph,row).
// =====================================================================
__device__ __forceinline__ void place_bits(unsigned nb, int cb, int& pos, int* __restrict__ row) {
    while (nb) {
        int b = __ffs(nb) - 1;
        nb &= nb - 1;
        if (pos < MAXD) row[pos] = cb + b;
        pos++;
    }
}

__global__ void csr_build(const float* __restrict__ m0, const float* __restrict__ m1) {
    int tid  = threadIdx.x;
    int w    = blockIdx.x * 8 + (tid >> 5);
    int lane = tid & 31;
    int g = w >> 12, r = w & 4095;
    const float4* mask = (const float4*)((g ? m1 : m0) + (size_t)r * N_NODES);
    int* row = &g_cols[g][r][0];
    int cnt = 0;
    for (int jb = 0; jb < 1024; jb += 128) {
        float4 v0 = mask[jb + lane];
        float4 v1 = mask[jb + 32 + lane];
        float4 v2 = mask[jb + 64 + lane];
        float4 v3 = mask[jb + 96 + lane];
        unsigned n0 = (v0.x > 0.f) | ((v0.y > 0.f) << 1) | ((v0.z > 0.f) << 2) | ((v0.w > 0.f) << 3);
        unsigned n1 = (v1.x > 0.f) | ((v1.y > 0.f) << 1) | ((v1.z > 0.f) << 2) | ((v1.w > 0.f) << 3);
        unsigned n2 = (v2.x > 0.f) | ((v2.y > 0.f) << 1) | ((v2.z > 0.f) << 2) | ((v2.w > 0.f) << 3);
        unsigned n3 = (v3.x > 0.f) | ((v3.y > 0.f) << 1) | ((v3.z > 0.f) << 2) | ((v3.w > 0.f) << 3);
        int c = __popc(n0) + __popc(n1) + __popc(n2) + __popc(n3);
        int s = c;
        #pragma unroll
        for (int off = 1; off < 32; off <<= 1) {
            int t = __shfl_up_sync(0xffffffffu, s, off);
            if (lane >= off) s += t;
        }
        int pos = cnt + s - c;
        cnt += __shfl_sync(0xffffffffu, s, 31);
        if (c) {
            place_bits(n0, (jb + lane) * 4,      pos, row);
            place_bits(n1, (jb + 32 + lane) * 4, pos, row);
            place_bits(n2, (jb + 64 + lane) * 4, pos, row);
            place_bits(n3, (jb + 96 + lane) * 4, pos, row);
        }
    }
    if (lane == 0) g_deg[g][r] = cnt < MAXD ? cnt : MAXD;
}

// =====================================================================
// GEMM1: Wh = x @ Wcat, tile 64x64, double-buffered, grid (64,8).
// 256 threads, microtile 4x4. + s1/s2 epilogue.   (round-9 proven)
// =====================================================================
__global__ void gemm1(const float* __restrict__ x,
                      const float* __restrict__ W1, const float* __restrict__ W2,
                      const float* __restrict__ a1, const float* __restrict__ a2) {
    __shared__ float As[2][16][68];
    __shared__ float Bs[2][16][64];
    int tid = threadIdx.x;
    int m0r = blockIdx.x * 64;
    int by  = blockIdx.y;                 // 0..7
    int gsel = by >> 2, h = by & 3;
    const float* W  = gsel ? W2 : W1;     // [4,256,64]
    const float* av = (gsel ? a2 : a1) + h * 128;
    int tx = tid & 15, ty = tid >> 4;

    int am = tid >> 2, ak4 = tid & 3;
    int bk = tid >> 4, bn = (tid & 15) * 4;
    const float* Aptr  = x + (size_t)(m0r + am) * FIN;
    const float* Bbase = W + (size_t)h * FIN * FHID;

    float4 fa = *(const float4*)(Aptr + ak4 * 4);
    float4 fb = *(const float4*)(Bbase + (size_t)bk * FHID + bn);
    As[0][ak4 * 4 + 0][am] = fa.x; As[0][ak4 * 4 + 1][am] = fa.y;
    As[0][ak4 * 4 + 2][am] = fa.z; As[0][ak4 * 4 + 3][am] = fa.w;
    *(float4*)&Bs[0][bk][bn] = fb;
    __syncthreads();

    float acc[4][4] = {};
    #pragma unroll
    for (int t = 0; t < 16; t++) {
        int cur = t & 1;
        if (t < 15) {
            int kb = (t + 1) * 16;
            fa = *(const float4*)(Aptr + kb + ak4 * 4);
            fb = *(const float4*)(Bbase + (size_t)(kb + bk) * FHID + bn);
        }
        #pragma unroll
        for (int kk = 0; kk < 16; kk++) {
            float a[4], b[4];
            #pragma unroll
            for (int r = 0; r < 4; r++) a[r] = As[cur][kk][ty * 4 + r];
            #pragma unroll
            for (int c = 0; c < 4; c++) b[c] = Bs[cur][kk][tx * 4 + c];
            #pragma unroll
            for (int r = 0; r < 4; r++)
                #pragma unroll
                for (int c = 0; c < 4; c++)
                    acc[r][c] += a[r] * b[c];
        }
        if (t < 15) {
            int nxt = cur ^ 1;
            As[nxt][ak4 * 4 + 0][am] = fa.x; As[nxt][ak4 * 4 + 1][am] = fa.y;
            As[nxt][ak4 * 4 + 2][am] = fa.z; As[nxt][ak4 * 4 + 3][am] = fa.w;
            *(float4*)&Bs[nxt][bk][bn] = fb;
        }
        __syncthreads();
    }

    int n0 = by * 64;
    #pragma unroll
    for (int r = 0; r < 4; r++) {
        int m = m0r + ty * 4 + r;
        float4 v = make_float4(acc[r][0], acc[r][1], acc[r][2], acc[r][3]);
        *(float4*)&g_Wh[m][n0 + tx * 4] = v;
    }
    float a_s[4], a_d[4];
    #pragma unroll
    for (int c = 0; c < 4; c++) {
        a_s[c] = __ldg(av + tx * 4 + c);
        a_d[c] = __ldg(av + 64 + tx * 4 + c);
    }
    #pragma unroll
    for (int r = 0; r < 4; r++) {
        float s1 = 0.f, s2 = 0.f;
        #pragma unroll
        for (int c = 0; c < 4; c++) { s1 += acc[r][c] * a_s[c]; s2 += acc[r][c] * a_d[c]; }
        #pragma unroll
        for (int off = 1; off < 16; off <<= 1) {
            s1 += __shfl_xor_sync(0xffffffffu, s1, off);
            s2 += __shfl_xor_sync(0xffffffffu, s2, off);
        }
        if (tx == 0) {
            int m = m0r + ty * 4 + r;
            g_s1t[gsel][m][h] = s1;
            g_s2t[gsel][m][h] = s2;
        }
    }
}

// ---- 4-head gather chunk (attn1) ----
__device__ __forceinline__ void gat_chunk1(const float* __restrict__ tab, int lim,
                                           int cj, float4 ej,
                                           float& ax0, float& ay0, float& ax1, float& ay1,
                                           float& ax2, float& ay2, float& ax3, float& ay3) {
    int kk = 0;
    for (; kk + 2 <= lim; kk += 2) {
        int   ca  = __shfl_sync(0xffffffffu, cj, kk);
        int   cb  = __shfl_sync(0xffffffffu, cj, kk + 1);
        float ea0 = __shfl_sync(0xffffffffu, ej.x, kk);
        float ea1 = __shfl_sync(0xffffffffu, ej.y, kk);
        float ea2 = __shfl_sync(0xffffffffu, ej.z, kk);
        float ea3 = __shfl_sync(0xffffffffu, ej.w, kk);
        float eb0 = __shfl_sync(0xffffffffu, ej.x, kk + 1);
        float eb1 = __shfl_sync(0xffffffffu, ej.y, kk + 1);
        float eb2 = __shfl_sync(0xffffffffu, ej.z, kk + 1);
        float eb3 = __shfl_sync(0xffffffffu, ej.w, kk + 1);
        const float* ra = tab + (size_t)ca * 512;
        const float* rb = tab + (size_t)cb * 512;
        float2 va0 = *(const float2*)(ra);
        float2 va1 = *(const float2*)(ra + 64);
        float2 va2 = *(const float2*)(ra + 128);
        float2 va3 = *(const float2*)(ra + 192);
        float2 vb0 = *(const float2*)(rb);
        float2 vb1 = *(const float2*)(rb + 64);
        float2 vb2 = *(const float2*)(rb + 128);
        float2 vb3 = *(const float2*)(rb + 192);
        ax0 += ea0 * va0.x + eb0 * vb0.x;  ay0 += ea0 * va0.y + eb0 * vb0.y;
        ax1 += ea1 * va1.x + eb1 * vb1.x;  ay1 += ea1 * va1.y + eb1 * vb1.y;
        ax2 += ea2 * va2.x + eb2 * vb2.x;  ay2 += ea2 * va2.y + eb2 * vb2.y;
        ax3 += ea3 * va3.x + eb3 * vb3.x;  ay3 += ea3 * va3.y + eb3 * vb3.y;
    }
    if (kk < lim) {
        int   ca  = __shfl_sync(0xffffffffu, cj, kk);
        float ea0 = __shfl_sync(0xffffffffu, ej.x, kk);
        float ea1 = __shfl_sync(0xffffffffu, ej.y, kk);
        float ea2 = __shfl_sync(0xffffffffu, ej.z, kk);
        float ea3 = __shfl_sync(0xffffffffu, ej.w, kk);
        const float* ra = tab + (size_t)ca * 512;
        float2 va0 = *(const float2*)(ra);
        float2 va1 = *(const float2*)(ra + 64);
        float2 va2 = *(const float2*)(ra + 128);
        float2 va3 = *(const float2*)(ra + 192);
        ax0 += ea0 * va0.x;  ay0 += ea0 * va0.y;
        ax1 += ea1 * va1.x;  ay1 += ea1 * va1.y;
        ax2 += ea2 * va2.x;  ay2 += ea2 * va2.y;
        ax3 += ea3 * va3.x;  ay3 += ea3 * va3.y;
    }
}

// =====================================================================
// Layer-1 attention: ONE warp per (node, graph), all 4 heads together.
// =====================================================================
__global__ void attn_layer1() {
    int tid  = threadIdx.x;
    int lane = tid & 31;
    int w    = tid >> 5;
    int n    = w >> 1;
    int g    = w & 1;
    int i    = blockIdx.x * 4 + n;

    int d = g_deg[g][i];
    float4 s1 = *(const float4*)&g_s1t[g][i][0];

    int c0 = 0, c1 = 0;
    float4 e0 = make_float4(0.f, 0.f, 0.f, 0.f);
    float4 e1 = make_float4(0.f, 0.f, 0.f, 0.f);
    if (lane < d) {
        c0 = g_cols[g][i][lane];
        float4 s2 = *(const float4*)&g_s2t[g][c0][0];
        e0.x = lkexp(s1.x + s2.x);  e0.y = lkexp(s1.y + s2.y);
        e0.z = lkexp(s1.z + s2.z);  e0.w = lkexp(s1.w + s2.w);
    }
    if (lane + 32 < d) {
        c1 = g_cols[g][i][lane + 32];
        float4 s2 = *(const float4*)&g_s2t[g][c1][0];
        e1.x = lkexp(s1.x + s2.x);  e1.y = lkexp(s1.y + s2.y);
        e1.z = lkexp(s1.z + s2.z);  e1.w = lkexp(s1.w + s2.w);
    }
    float sx = e0.x + e1.x, sy = e0.y + e1.y, sz = e0.z + e1.z, sw = e0.w + e1.w;
    #pragma unroll
    for (int off = 16; off; off >>= 1) {
        sx += __shfl_xor_sync(0xffffffffu, sx, off);
        sy += __shfl_xor_sync(0xffffffffu, sy, off);
        sz += __shfl_xor_sync(0xffffffffu, sz, off);
        sw += __shfl_xor_sync(0xffffffffu, sw, off);
    }
    float ix = 1.f / sx, iy = 1.f / sy, iz = 1.f / sz, iw = 1.f / sw;

    const float* tab = &g_Wh[0][g * 256 + 2 * lane];
    float ax0 = 0.f, ay0 = 0.f, ax1 = 0.f, ay1 = 0.f;
    float ax2 = 0.f, ay2 = 0.f, ax3 = 0.f, ay3 = 0.f;
    int lim0 = d < 32 ? d : 32;
    int lim1 = d - 32; lim1 = lim1 < 0 ? 0 : lim1;
    gat_chunk1(tab, lim0, c0, e0, ax0, ay0, ax1, ay1, ax2, ay2, ax3, ay3);
    gat_chunk1(tab, lim1, c1, e1, ax0, ay0, ax1, ay1, ax2, ay2, ax3, ay3);

    float* orow = &g_hcat[g][i][2 * lane];
    float2 o;
    o.x = elu1(ax0 * ix);  o.y = elu1(ay0 * ix);  *(float2*)(orow)       = o;
    o.x = elu1(ax1 * iy);  o.y = elu1(ay1 * iy);  *(float2*)(orow + 64)  = o;
    o.x = elu1(ax2 * iz);  o.y = elu1(ay2 * iz);  *(float2*)(orow + 128) = o;
    o.x = elu1(ax3 * iw);  o.y = elu1(ay3 * iw);  *(float2*)(orow + 192) = o;
}

// =====================================================================
// GEMM2 (K-split): Wh2_g = hcat_g @ Wo_g, tile 32x64, 256 threads =
// 2 k-groups x 128; each group 4x4 microtile over K/2, smem reduce.
// grid (128, 2), double-buffered. + s1o/s2o epilogue.
// =====================================================================
__global__ void __launch_bounds__(256) gemm2f(
        const float* __restrict__ Wo1, const float* __restrict__ Wo2,
        const float* __restrict__ ao1, const float* __restrict__ ao2) {
    __shared__ float As[2][2][16][36];   // [kg][buf][k][m]
    __shared__ float Bs[2][2][16][64];   // [kg][buf][k][n]
    __shared__ float red[32][64];
    int g = blockIdx.y;
    int m0r = blockIdx.x * 32;
    const float* A  = &g_hcat[g][0][0];
    const float* B  = g ? Wo2 : Wo1;
    const float* ao = g ? ao2 : ao1;
    int tid  = threadIdx.x;
    int kg   = tid >> 7;                  // 0/1: K halves
    int tloc = tid & 127;
    int tx = tloc & 15, ty = tloc >> 4;   // ty 0..7
    int am = tloc >> 2, ak4 = tloc & 3;   // A loaders: 128 f4
    int bk0 = tloc >> 4, bc0 = (tloc & 15) * 4;
    int bk1 = (128 + tloc) >> 4, bc1 = ((128 + tloc) & 15) * 4;
    int kbase = kg * 128;
    const float* Aptr = A + (size_t)(m0r + am) * 256 + kbase;
    const float* Bptr = B + (size_t)kbase * 64;

    float4 fa  = *(const float4*)(Aptr + ak4 * 4);
    float4 fb0 = *(const float4*)(Bptr + (size_t)bk0 * 64 + bc0);
    float4 fb1 = *(const float4*)(Bptr + (size_t)bk1 * 64 + bc1);
    As[kg][0][ak4 * 4 + 0][am] = fa.x; As[kg][0][ak4 * 4 + 1][am] = fa.y;
    As[kg][0][ak4 * 4 + 2][am] = fa.z; As[kg][0][ak4 * 4 + 3][am] = fa.w;
    *(float4*)&Bs[kg][0][bk0][bc0] = fb0;
    *(float4*)&Bs[kg][0][bk1][bc1] = fb1;
    __syncthreads();

    float acc[4][4] = {};
    #pragma unroll
    for (int t = 0; t < 8; t++) {
        int cur = t & 1;
        if (t < 7) {
            int kb = (t + 1) * 16;
            fa  = *(const float4*)(Aptr + kb + ak4 * 4);
            fb0 = *(const float4*)(Bptr + (size_t)(kb + bk0) * 64 + bc0);
            fb1 = *(const float4*)(Bptr + (size_t)(kb + bk1) * 64 + bc1);
        }
        #pragma unroll
        for (int kk = 0; kk < 16; kk++) {
            float4 av = *(const float4*)&As[kg][cur][kk][ty * 4];
            float4 bv = *(const float4*)&Bs[kg][cur][kk][tx * 4];
            float a[4] = {av.x, av.y, av.z, av.w};
            float b[4] = {bv.x, bv.y, bv.z, bv.w};
            #pragma unroll
            for (int r = 0; r < 4; r++)
                #pragma unroll
                for (int c = 0; c < 4; c++)
                    acc[r][c] += a[r] * b[c];
        }
        if (t < 7) {
            int nxt = cur ^ 1;
            As[kg][nxt][ak4 * 4 + 0][am] = fa.x; As[kg][nxt][ak4 * 4 + 1][am] = fa.y;
            As[kg][nxt][ak4 * 4 + 2][am] = fa.z; As[kg][nxt][ak4 * 4 + 3][am] = fa.w;
            *(float4*)&Bs[kg][nxt][bk0][bc0] = fb0;
            *(float4*)&Bs[kg][nxt][bk1][bc1] = fb1;
        }
        __syncthreads();
    }

    // kg1 publishes partials, kg0 reduces + epilogue
    if (kg == 1) {
        #pragma unroll
        for (int r = 0; r < 4; r++) {
            float4 v = make_float4(acc[r][0], acc[r][1], acc[r][2], acc[r][3]);
            *(float4*)&red[ty * 4 + r][tx * 4] = v;
        }
    }
    __syncthreads();
    if (kg == 0) {
        #pragma unroll
        for (int r = 0; r < 4; r++) {
            float4 v = *(const float4*)&red[ty * 4 + r][tx * 4];
            acc[r][0] += v.x; acc[r][1] += v.y; acc[r][2] += v.z; acc[r][3] += v.w;
        }
        #pragma unroll
        for (int r = 0; r < 4; r++) {
            int m = m0r + ty * 4 + r;
            float4 v = make_float4(acc[r][0], acc[r][1], acc[r][2], acc[r][3]);
            *(float4*)&g_Wh2[g][m][tx * 4] = v;
        }
        float a_s[4], a_d[4];
        #pragma unroll
        for (int c = 0; c < 4; c++) {
            a_s[c] = __ldg(ao + tx * 4 + c);
            a_d[c] = __ldg(ao + 64 + tx * 4 + c);
        }
        #pragma unroll
        for (int r = 0; r < 4; r++) {
            float s1 = 0.f, s2 = 0.f;
            #pragma unroll
            for (int c = 0; c < 4; c++) { s1 += acc[r][c] * a_s[c]; s2 += acc[r][c] * a_d[c]; }
            #pragma unroll
            for (int off = 1; off < 16; off <<= 1) {
                s1 += __shfl_xor_sync(0xffffffffu, s1, off);
                s2 += __shfl_xor_sync(0xffffffffu, s2, off);
            }
            if (tx == 0) {
                int m = m0r + ty * 4 + r;
                g_s1o[g][m] = s1;
                g_s2o[g][m] = s2;
            }
        }
    }
}

// ---- scalar gather chunk (attn2), MLP=4, stride 64 floats ----
__device__ __forceinline__ void gat_chunk2(const float* __restrict__ tab, int lim,
                                           int cj, float ej, float& ax, float& ay) {
    int kk = 0;
    for (; kk + 4 <= lim; kk += 4) {
        int   c0 = __shfl_sync(0xffffffffu, cj, kk);
        int   c1 = __shfl_sync(0xffffffffu, cj, kk + 1);
        int   c2 = __shfl_sync(0xffffffffu, cj, kk + 2);
        int   c3 = __shfl_sync(0xffffffffu, cj, kk + 3);
        float e0 = __shfl_sync(0xffffffffu, ej, kk);
        float e1 = __shfl_sync(0xffffffffu, ej, kk + 1);
        float e2 = __shfl_sync(0xffffffffu, ej, kk + 2);
        float e3 = __shfl_sync(0xffffffffu, ej, kk + 3);
        float2 v0 = *(const float2*)(tab + (size_t)c0 * 64);
        float2 v1 = *(const float2*)(tab + (size_t)c1 * 64);
        float2 v2 = *(const float2*)(tab + (size_t)c2 * 64);
        float2 v3 = *(const float2*)(tab + (size_t)c3 * 64);
        ax += e0 * v0.x + e1 * v1.x + e2 * v2.x + e3 * v3.x;
        ay += e0 * v0.y + e1 * v1.y + e2 * v2.y + e3 * v3.y;
    }
    for (; kk < lim; kk++) {
        int   c = __shfl_sync(0xffffffffu, cj, kk);
        float e = __shfl_sync(0xffffffffu, ej, kk);
        float2 v = *(const float2*)(tab + (size_t)c * 64);
        ax += e * v.x;
        ay += e * v.y;
    }
}

// =====================================================================
// Layer-2 attention + ELU + semantic fusion.
// =====================================================================
__global__ void attn2_final(const float* __restrict__ Wp1, const float* __restrict__ bp1,
                            const float* __restrict__ Wp2, float* __restrict__ out) {
    int tid  = threadIdx.x;
    int lane = tid & 31;
    int w    = tid >> 5;        // 0..7
    int n    = w >> 1;          // node slot 0..3
    int g    = w & 1;
    int i    = blockIdx.x * 4 + n;

    __shared__ float se[4][2][64];
    __shared__ float sw[4][2];

    int d = g_deg[g][i];
    float s1v = g_s1o[g][i];
    int c0 = 0, c1 = 0;
    float e0 = 0.f, e1 = 0.f;
    if (lane < d) {
        c0 = g_cols[g][i][lane];
        e0 = lkexp(s1v + g_s2o[g][c0]);
    }
    if (lane + 32 < d) {
        c1 = g_cols[g][i][lane + 32];
        e1 = lkexp(s1v + g_s2o[g][c1]);
    }
    float sum = e0 + e1;
    #pragma unroll
    for (int off = 16; off; off >>= 1) sum += __shfl_xor_sync(0xffffffffu, sum, off);
    float inv = 1.f / sum;

    const float* tab = &g_Wh2[g][0][2 * lane];
    float ax = 0.f, ay = 0.f;
    int lim0 = d < 32 ? d : 32;
    int lim1 = d - 32; lim1 = lim1 < 0 ? 0 : lim1;
    gat_chunk2(tab, lim0, c0, e0, ax, ay);
    gat_chunk2(tab, lim1, c1, e1, ax, ay);

    ax *= inv; ay *= inv;
    se[n][g][2 * lane]     = elu1(ax);
    se[n][g][2 * lane + 1] = elu1(ay);
    __syncthreads();

    if (tid < 128) {
        int pn = tid >> 5, pg = (tid >> 4) & 1, p = tid & 15;
        float s = __ldg(bp1 + p);
        #pragma unroll
        for (int f = 0; f < 64; f++) s += se[pn][pg][f] * __ldg(Wp1 + f * NPROJ + p);
        float e2x = __expf(2.f * s);
        float t = __fdividef(e2x - 1.f, e2x + 1.f);
        float wv = t * __ldg(Wp2 + p);
        wv += __shfl_xor_sync(0xffffffffu, wv, 1);
        wv += __shfl_xor_sync(0xffffffffu, wv, 2);
        wv += __shfl_xor_sync(0xffffffffu, wv, 4);
        wv += __shfl_xor_sync(0xffffffffu, wv, 8);
        if (p == 0) sw[pn][pg] = wv;
    }
    __syncthreads();

    int on = tid >> 6, f = tid & 63;
    float w0 = sw[on][0], w1 = sw[on][1];
    float mm = fmaxf(w0, w1);
    float b0 = __expf(w0 - mm), b1 = __expf(w1 - mm);
    float ib = 1.f / (b0 + b1);
    int oi = blockIdx.x * 4 + on;
    out[(size_t)oi * 64 + f] = (b0 * se[on][0][f] + b1 * se[on][1][f]) * ib;
}

// ---------------- launch ----------------
extern "C" void kernel_launch(void* const* d_in, const int* in_sizes, int n_in,
                              void* d_out, int out_size) {
    const float* x    = (const float*)d_in[0];
    const float* sadj = (const float*)d_in[1];
    const float* sadj2= (const float*)d_in[2];
    const float* W1   = (const float*)d_in[3];
    const float* a1   = (const float*)d_in[4];
    const float* Wo1  = (const float*)d_in[5];
    const float* ao1  = (const float*)d_in[6];
    const float* W2   = (const float*)d_in[7];
    const float* a2   = (const float*)d_in[8];
    const float* Wo2  = (const float*)d_in[9];
    const float* ao2  = (const float*)d_in[10];
    const float* Wp1  = (const float*)d_in[11];
    const float* bp1  = (const float*)d_in[12];
    const float* Wp2  = (const float*)d_in[13];
    float* out = (float*)d_out;

    // side stream + events (created once, before any graph capture;
    // replays reuse the captured fork/join — no per-call allocation)
    static cudaStream_t s_side = nullptr;
    static cudaEvent_t  ev_fork = nullptr, ev_join = nullptr;
    if (!s_side) {
        cudaStreamCreateWithFlags(&s_side, cudaStreamNonBlocking);
        cudaEventCreateWithFlags(&ev_fork, cudaEventDisableTiming);
        cudaEventCreateWithFlags(&ev_join, cudaEventDisableTiming);
    }

    // fork: csr_build (DRAM-bound) runs concurrently with gemm1 (FMA-bound)
    cudaEventRecord(ev_fork, 0);
    cudaStreamWaitEvent(s_side, ev_fork, 0);
    csr_build<<<1024, 256, 0, s_side>>>(sadj, sadj2);
    cudaEventRecord(ev_join, s_side);

    gemm1<<<dim3(64, 8), 256>>>(x, W1, W2, a1, a2);

    // join before attention (needs both g_cols and g_Wh/s1t/s2t)
    cudaStreamWaitEvent(0, ev_join, 0);

    attn_layer1<<<1024, 256>>>();
    gemm2f<<<dim3(128, 2), 256>>>(Wo1, Wo2, ao1, ao2);
    attn2_final<<<1024, 256>>>(Wp1, bp1, Wp2, out);
}